// round 1
// baseline (speedup 1.0000x reference)
#include <cuda_runtime.h>
#include <cstdint>

// Problem constants
#define BDIM   16
#define NDIM   128
#define EDIM   127
#define MDIM   16
#define BN     2048                 // B*N
#define BNE    260096               // B*N*E

// Compute kernel config
#define CK_THREADS 512
#define CK_NODES   16               // nodes per block
#define CK_BLOCKS  (BN / CK_NODES)  // 128
#define WPAD       36               // padded row width for Wsm (conflict-free LDS.128)

// Smem layout (floats)
#define OFF_WSM    0
#define OFF_B3S    (OFF_WSM + 256*WPAD)       // 9216
#define OFF_H2S    (OFF_B3S + 256)            // 9472
#define OFF_W2S    (OFF_H2S + CK_NODES*4*32)  // 11520
#define OFF_S0S    (OFF_W2S + 4*32*33)        // 15744
#define OFF_C00    (OFF_S0S + CK_NODES*16)    // 16000
#define OFF_WS1    (OFF_C00 + CK_NODES*16)    // 16256
#define OFF_V11    (OFF_WS1 + CK_NODES*16)    // 16512
#define OFF_B01    (OFF_V11 + CK_NODES*3*48)  // 18816
#define OFF_MSG    (OFF_B01 + CK_NODES*3)     // 18864
#define SMEM_FLOATS (OFF_MSG + CK_NODES*64)   // 19888
#define SMEM_BYTES (SMEM_FLOATS * 4)          // 79552

// Per-node message scratch: [2048][64] = msg0[16] | msg1[48]
__device__ float g_msg[BN * 64];

__device__ __forceinline__ float warp_sum(float v) {
    v += __shfl_xor_sync(0xffffffffu, v, 16);
    v += __shfl_xor_sync(0xffffffffu, v, 8);
    v += __shfl_xor_sync(0xffffffffu, v, 4);
    v += __shfl_xor_sync(0xffffffffu, v, 2);
    v += __shfl_xor_sync(0xffffffffu, v, 1);
    return v;
}

#define DOT4(acc, h, wv) do { \
    acc = fmaf((h).x, (wv).x, acc); \
    acc = fmaf((h).y, (wv).y, acc); \
    acc = fmaf((h).z, (wv).z, acc); \
    acc = fmaf((h).w, (wv).w, acc); } while (0)

extern "C" __global__ void __launch_bounds__(CK_THREADS, 1)
compute_kernel(const float* __restrict__ r,
               const float* __restrict__ src0,
               const float* __restrict__ src1,
               const float* __restrict__ b00g,
               const float* __restrict__ b01g,
               const float* __restrict__ b10g,
               const float* __restrict__ b11g,
               const float* __restrict__ w1,
               const float* __restrict__ b1,
               const float* __restrict__ g1,
               const float* __restrict__ be1,
               const float* __restrict__ w2,
               const float* __restrict__ b2,
               const float* __restrict__ g2,
               const float* __restrict__ be2,
               const float* __restrict__ w300, const float* __restrict__ b300,
               const float* __restrict__ w301, const float* __restrict__ b301,
               const float* __restrict__ w310, const float* __restrict__ b310,
               const float* __restrict__ w311, const float* __restrict__ b311)
{
    extern __shared__ float sm[];
    float* Wsm   = sm + OFF_WSM;
    float* b3s   = sm + OFF_B3S;
    float* h2s   = sm + OFF_H2S;
    float* w2s   = sm + OFF_W2S;
    float* s0s   = sm + OFF_S0S;
    float* c00s  = sm + OFF_C00;
    float* ws1s  = sm + OFF_WS1;
    float* v11s  = sm + OFF_V11;
    float* b01sm = sm + OFF_B01;
    float* msgAcc= sm + OFF_MSG;

    const int t    = threadIdx.x;
    const int lane = t & 31;
    const int w    = t >> 5;           // warp id = node-in-block (prologue)
    const int blk  = blockIdx.x;

    // ---- stage w2 into smem (padded 33), zero msg accumulators ----
    for (int idx = t; idx < 4096; idx += CK_THREADS) {
        int m  = idx >> 10;
        int rem = idx & 1023;
        int k  = rem >> 5;
        int k2 = rem & 31;
        w2s[(m * 32 + k) * 33 + k2] = w2[idx];
    }
    for (int idx = t; idx < CK_NODES * 64; idx += CK_THREADS) msgAcc[idx] = 0.f;
    __syncthreads();

    // ---- prologue: warp w computes MLP front (h2) + aux for node (blk*16+w) ----
    const int node = blk * CK_NODES + w;
    const int eb   = node * EDIM;          // first edge of node
    const float x  = r[eb];
    const int k    = lane;

    #pragma unroll
    for (int m = 0; m < 4; m++) {
        // layer1 + LN + relu
        float v = fmaf(x, w1[m * 32 + k], b1[m * 32 + k]);
        float mu = warp_sum(v) * (1.f / 32.f);
        float d = v - mu;
        float var = warp_sum(d * d) * (1.f / 32.f);
        v = fmaf(d * rsqrtf(var + 1e-5f), g1[m * 32 + k], be1[m * 32 + k]);
        v = fmaxf(v, 0.f);
        // layer2 (shuffle-broadcast dot) + LN + relu
        float acc = b2[m * 32 + k];
        const float* wr = &w2s[(m * 32 + k) * 33];
        #pragma unroll
        for (int kk = 0; kk < 32; kk++)
            acc = fmaf(__shfl_sync(0xffffffffu, v, kk), wr[kk], acc);
        mu = warp_sum(acc) * (1.f / 32.f);
        d = acc - mu;
        var = warp_sum(d * d) * (1.f / 32.f);
        acc = fmaf(d * rsqrtf(var + 1e-5f), g2[m * 32 + k], be2[m * 32 + k]);
        acc = fmaxf(acc, 0.f);
        h2s[(w * 4 + m) * 32 + k] = acc;
    }

    if (lane < 16) {
        const int j = lane;
        float s0v = src0[eb * 16 + j];
        float s1a = src1[eb * 48 + j * 3 + 0];
        float s1b = src1[eb * 48 + j * 3 + 1];
        float s1c = src1[eb * 48 + j * 3 + 2];
        float bb00 = b00g[node];
        s0s[w * 16 + j] = s0v;
        c00s[w * 16 + j] = bb00 * s0v;
        ws1s[w * 16 + j] = b10g[node * 3 + 0] * s1a
                         + b10g[node * 3 + 1] * s1b
                         + b10g[node * 3 + 2] * s1c;
        #pragma unroll
        for (int a = 0; a < 3; a++) {
            #pragma unroll
            for (int f = 0; f < 3; f++) {
                float vv = b11g[node * 27 + a * 9 + 0 * 3 + f] * s1a
                         + b11g[node * 27 + a * 9 + 1 * 3 + f] * s1b
                         + b11g[node * 27 + a * 9 + 2 * 3 + f] * s1c;
                v11s[(w * 3 + a) * 48 + j * 3 + f] = vv;
            }
        }
        if (j < 3) b01sm[w * 3 + j] = b01g[node * 3 + j];
    }
    __syncthreads();

    // ---- main GEMM + fused contraction ----
    // warp w: nodes pA = 2*(w&7), pB = pA+1; row-half = w>>3
    const int pA = (w & 7) * 2;
    const int pB = pA + 1;
    const int half = w >> 3;
    const int li = lane & 15;   // i index (permuted rows: i fastest)
    const int hi = lane >> 4;

    const float bA0 = b01sm[pA * 3 + 0], bA1 = b01sm[pA * 3 + 1], bA2 = b01sm[pA * 3 + 2];
    const float bB0 = b01sm[pB * 3 + 0], bB1 = b01sm[pB * 3 + 1], bB2 = b01sm[pB * 3 + 2];

    float a0A = 0.f, a0B = 0.f;
    float a1A0 = 0.f, a1A1 = 0.f, a1A2 = 0.f;
    float a1B0 = 0.f, a1B1 = 0.f, a1B2 = 0.f;

    for (int ch = 0; ch < 6; ch++) {
        const float* w3sel = (ch == 0) ? w300 : (ch == 1) ? w301 : (ch == 2) ? w310 : w311;
        const float* b3sel = (ch == 0) ? b300 : (ch == 1) ? b301 : (ch == 2) ? b310 : b311;
        const int cc = (ch >= 3) ? (ch - 3) : 0;
        const bool is11 = (ch >= 3);

        // stage 256 permuted rows: smem row rp holds source row (rp&15)*stride + (rp>>4)
        const float4* w3sel4 = (const float4*)w3sel;
        for (int d4 = t; d4 < 2048; d4 += CK_THREADS) {
            int rowp = d4 >> 3, k4 = d4 & 7;
            int ii = rowp & 15, g = rowp >> 4;
            int srow = is11 ? (ii * 48 + cc * 16 + g) : (ii * 16 + g);
            float4 vv = w3sel4[srow * 8 + k4];
            *(float4*)&Wsm[rowp * WPAD + k4 * 4] = vv;
        }
        if (t < 256) {
            int ii = t & 15, g = t >> 4;
            int srow = is11 ? (ii * 48 + cc * 16 + g) : (ii * 16 + g);
            b3s[t] = b3sel[srow];
        }
        __syncthreads();

        const int m = (ch < 3) ? ch : 3;
        float4 hA4[8], hB4[8];
        const float4* ha = (const float4*)&h2s[(pA * 4 + m) * 32];
        const float4* hb = (const float4*)&h2s[(pB * 4 + m) * 32];
        #pragma unroll
        for (int q = 0; q < 8; q++) { hA4[q] = ha[q]; hB4[q] = hb[q]; }

        #pragma unroll
        for (int rr = 0; rr < 4; rr++) {
            const int rowp = half * 128 + rr * 32 + lane;
            const float bb = b3s[rowp];
            const float4* wr4 = (const float4*)&Wsm[rowp * WPAD];
            float vA0 = bb, vA1 = 0.f, vB0 = bb, vB1 = 0.f;
            #pragma unroll
            for (int q = 0; q < 8; q += 2) {
                float4 wv0 = wr4[q];
                float4 wv1 = wr4[q + 1];
                DOT4(vA0, hA4[q], wv0);
                DOT4(vB0, hB4[q], wv0);
                DOT4(vA1, hA4[q + 1], wv1);
                DOT4(vB1, hB4[q + 1], wv1);
            }
            const float vA = vA0 + vA1;
            const float vB = vB0 + vB1;
            const int g = half * 8 + rr * 2 + hi;   // = rowp>>4

            if (ch == 0) {
                a0A = fmaf(vA, c00s[pA * 16 + g], a0A);
                a0B = fmaf(vB, c00s[pB * 16 + g], a0B);
            } else if (ch == 1) {
                float tA = vA * s0s[pA * 16 + g];
                float tB = vB * s0s[pB * 16 + g];
                a1A0 = fmaf(tA, bA0, a1A0); a1A1 = fmaf(tA, bA1, a1A1); a1A2 = fmaf(tA, bA2, a1A2);
                a1B0 = fmaf(tB, bB0, a1B0); a1B1 = fmaf(tB, bB1, a1B1); a1B2 = fmaf(tB, bB2, a1B2);
            } else if (ch == 2) {
                a0A = fmaf(vA, ws1s[pA * 16 + g], a0A);
                a0B = fmaf(vB, ws1s[pB * 16 + g], a0B);
            } else {
                const int gg = cc * 16 + g;
                a1A0 = fmaf(vA, v11s[(pA * 3 + 0) * 48 + gg], a1A0);
                a1A1 = fmaf(vA, v11s[(pA * 3 + 1) * 48 + gg], a1A1);
                a1A2 = fmaf(vA, v11s[(pA * 3 + 2) * 48 + gg], a1A2);
                a1B0 = fmaf(vB, v11s[(pB * 3 + 0) * 48 + gg], a1B0);
                a1B1 = fmaf(vB, v11s[(pB * 3 + 1) * 48 + gg], a1B1);
                a1B2 = fmaf(vB, v11s[(pB * 3 + 2) * 48 + gg], a1B2);
            }
        }
        __syncthreads();
    }

    // ---- reduce lane-pairs (xor 16) and accumulate into smem messages ----
    a0A  += __shfl_xor_sync(0xffffffffu, a0A, 16);
    a0B  += __shfl_xor_sync(0xffffffffu, a0B, 16);
    a1A0 += __shfl_xor_sync(0xffffffffu, a1A0, 16);
    a1A1 += __shfl_xor_sync(0xffffffffu, a1A1, 16);
    a1A2 += __shfl_xor_sync(0xffffffffu, a1A2, 16);
    a1B0 += __shfl_xor_sync(0xffffffffu, a1B0, 16);
    a1B1 += __shfl_xor_sync(0xffffffffu, a1B1, 16);
    a1B2 += __shfl_xor_sync(0xffffffffu, a1B2, 16);

    if (lane < 16) {
        atomicAdd(&msgAcc[pA * 64 + li], a0A);
        atomicAdd(&msgAcc[pB * 64 + li], a0B);
        atomicAdd(&msgAcc[pA * 64 + 16 + li * 3 + 0], a1A0);
        atomicAdd(&msgAcc[pA * 64 + 16 + li * 3 + 1], a1A1);
        atomicAdd(&msgAcc[pA * 64 + 16 + li * 3 + 2], a1A2);
        atomicAdd(&msgAcc[pB * 64 + 16 + li * 3 + 0], a1B0);
        atomicAdd(&msgAcc[pB * 64 + 16 + li * 3 + 1], a1B1);
        atomicAdd(&msgAcc[pB * 64 + 16 + li * 3 + 2], a1B2);
    }
    __syncthreads();

    for (int idx = t; idx < CK_NODES * 64; idx += CK_THREADS)
        g_msg[blk * (CK_NODES * 64) + idx] = msgAcc[idx];
}

// ---- broadcast: per-node message -> all 127 edges, vectorized float4 stores ----
#define OUT1_BASE4 1040384   // (BNE*16)/4

extern "C" __global__ void __launch_bounds__(256)
broadcast_kernel(float4* __restrict__ out)
{
    const int bn = blockIdx.x;
    const int t  = threadIdx.x;
    __shared__ float4 m1q[12];

    const float4* mg = (const float4*)(g_msg + bn * 64);
    float4 m0[4];
    #pragma unroll
    for (int q = 0; q < 4; q++) m0[q] = mg[q];
    if (t < 12) m1q[t] = mg[4 + t];
    __syncthreads();

    // out0: node slice = 127 edges * 16 floats = 508 float4, period 4
    float4* o0 = out + bn * 508;
    #pragma unroll
    for (int i4 = t; i4 < 508; i4 += 256) o0[i4] = m0[i4 & 3];

    // out1: node slice = 127 edges * 48 floats = 1524 float4, period 12
    float4* o1 = out + OUT1_BASE4 + bn * 1524;
    for (int i4 = t; i4 < 1524; i4 += 256) o1[i4] = m1q[i4 % 12];
}

extern "C" void kernel_launch(void* const* d_in, const int* in_sizes, int n_in,
                              void* d_out, int out_size)
{
    const float* r    = (const float*)d_in[0];
    const float* src0 = (const float*)d_in[1];
    const float* src1 = (const float*)d_in[2];
    const float* b00  = (const float*)d_in[3];
    const float* b01  = (const float*)d_in[4];
    const float* b10  = (const float*)d_in[5];
    const float* b11  = (const float*)d_in[6];
    const float* w1   = (const float*)d_in[7];
    const float* b1   = (const float*)d_in[8];
    const float* g1   = (const float*)d_in[9];
    const float* be1  = (const float*)d_in[10];
    const float* w2   = (const float*)d_in[11];
    const float* b2   = (const float*)d_in[12];
    const float* g2   = (const float*)d_in[13];
    const float* be2  = (const float*)d_in[14];
    const float* w300 = (const float*)d_in[15];
    const float* b300 = (const float*)d_in[16];
    const float* w301 = (const float*)d_in[17];
    const float* b301 = (const float*)d_in[18];
    const float* w310 = (const float*)d_in[19];
    const float* b310 = (const float*)d_in[20];
    const float* w311 = (const float*)d_in[21];
    const float* b311 = (const float*)d_in[22];

    cudaFuncSetAttribute(compute_kernel,
                         cudaFuncAttributeMaxDynamicSharedMemorySize, SMEM_BYTES);

    compute_kernel<<<CK_BLOCKS, CK_THREADS, SMEM_BYTES>>>(
        r, src0, src1, b00, b01, b10, b11,
        w1, b1, g1, be1, w2, b2, g2, be2,
        w300, b300, w301, b301, w310, b310, w311, b311);

    broadcast_kernel<<<BN, 256>>>((float4*)d_out);
}